// round 9
// baseline (speedup 1.0000x reference)
#include <cuda_runtime.h>

// Problem dims (fixed per reference)
#define TT 512
#define BB 64
#define II 768
#define DD 2048
#define LEAK 0.5f

// Stage-2 persistent-kernel config
#define S2_NCTA 128           // 2048 / 16 d-tiles; <=148 SMs -> persistent
#define S2_DTILE 16
#define S2_KT 64
#define S2_THREADS 256
#define S2_NCHUNK (DD / S2_KT)

// Scratch (__device__ globals; no allocations allowed)
__device__ float g_hT[2][DD * BB];      // hidden state TRANSPOSED: [d][b], double-buffered
__device__ float g_Wt[DD * DD];         // res_w transposed: Wt[k][d] = res_w[d][k]  (16 MB)
__device__ unsigned int g_bar[TT];      // per-step grid-barrier counters

// ---------------------------------------------------------------------------
// Packed f32x2 helpers (Blackwell dual-lane fp32 FMA: 2x fp32 throughput)
// ---------------------------------------------------------------------------
__device__ __forceinline__ void ffma2(unsigned long long& acc,
                                      unsigned long long a,
                                      unsigned long long b) {
    asm("fma.rn.f32x2 %0, %1, %2, %0;" : "+l"(acc) : "l"(a), "l"(b));
}
__device__ __forceinline__ unsigned long long pack2(float x) {
    unsigned long long r; unsigned int u = __float_as_uint(x);
    asm("mov.b64 %0, {%1, %2};" : "=l"(r) : "r"(u), "r"(u));
    return r;
}
__device__ __forceinline__ void unpack2(unsigned long long v, float& lo, float& hi) {
    unsigned int a, b;
    asm("mov.b64 {%0, %1}, %2;" : "=r"(a), "=r"(b) : "l"(v));
    lo = __uint_as_float(a); hi = __uint_as_float(b);
}

__device__ __forceinline__ float fast_tanh(float x) {
    // 1 - 2/(e^{2x}+1): exact +/-1 at saturation
    float e = __expf(2.0f * x);
    return 1.0f - 2.0f / (e + 1.0f);
}

// ---------------------------------------------------------------------------
// Init: zero h0 (both buffers) and barrier counters — every replay
// ---------------------------------------------------------------------------
__global__ void init_kernel() {
    int idx = blockIdx.x * blockDim.x + threadIdx.x;
    int stride = gridDim.x * blockDim.x;
    float* h = (float*)g_hT;
    for (int i = idx; i < 2 * DD * BB; i += stride) h[i] = 0.0f;
    for (int i = idx; i < TT; i += stride) g_bar[i] = 0u;
}

// ---------------------------------------------------------------------------
// Transpose res_w [d][k] -> g_Wt [k][d]  (32x32 tiled)
// ---------------------------------------------------------------------------
__global__ __launch_bounds__(256) void transpose_kernel(const float* __restrict__ W) {
    __shared__ float tile[32][33];
    const int bk = blockIdx.x * 32;   // k-block
    const int bd = blockIdx.y * 32;   // d-block
    const int tx = threadIdx.x & 31;
    const int ty = threadIdx.x >> 5;  // 0..7
#pragma unroll
    for (int i = 0; i < 32; i += 8)
        tile[ty + i][tx] = W[(size_t)(bd + ty + i) * DD + bk + tx];
    __syncthreads();
#pragma unroll
    for (int i = 0; i < 32; i += 8)
        g_Wt[(size_t)(bk + ty + i) * DD + bd + tx] = tile[tx][ty + i];
}

// ---------------------------------------------------------------------------
// Stage 1: proj[t,b,n] = sum_k batch[t,b,k]*W_in[n,k] + bias[n], into out[b,t,n]
// CTA tile 64m x 128n, k-tile 16, 256 threads, microtile 4m x 8n via f32x2.
// ---------------------------------------------------------------------------
__global__ __launch_bounds__(256) void proj_kernel(
    const float* __restrict__ A,      // [TT*BB, II]
    const float* __restrict__ W,      // [DD, II]
    const float* __restrict__ bias,
    float* __restrict__ out)          // [BB, TT, DD]
{
    __shared__ __align__(16) float As[16][68];    // [k][m]
    __shared__ __align__(16) float Bs[16][136];   // [k][n]

    const int m0 = blockIdx.y * 64;     // = t * 64 (m-tile == BB)
    const int n0 = blockIdx.x * 128;
    const int tid = threadIdx.x;
    const int tn = tid & 15;            // n-group: 8 n each
    const int tm = tid >> 4;            // m-group: 4 m each

    // loaders
    const int am = tid >> 2, aq = tid & 3;   // A: m row, k-quad
    const int bn = tid >> 1, br = tid & 1;   // B: n row, k-oct

    unsigned long long acc[4][4];
#pragma unroll
    for (int i = 0; i < 4; i++)
#pragma unroll
        for (int j = 0; j < 4; j++) acc[i][j] = 0ull;

    const float* Aptr = A + (size_t)(m0 + am) * II + aq * 4;
    const float* Wptr = W + (size_t)(n0 + bn) * II + br * 8;

    float4 a_reg  = *(const float4*)(Aptr);
    float4 b_reg0 = *(const float4*)(Wptr);
    float4 b_reg1 = *(const float4*)(Wptr + 4);

    for (int k0 = 0; k0 < II; k0 += 16) {
        As[aq * 4 + 0][am] = a_reg.x;
        As[aq * 4 + 1][am] = a_reg.y;
        As[aq * 4 + 2][am] = a_reg.z;
        As[aq * 4 + 3][am] = a_reg.w;
        Bs[br * 8 + 0][bn] = b_reg0.x;
        Bs[br * 8 + 1][bn] = b_reg0.y;
        Bs[br * 8 + 2][bn] = b_reg0.z;
        Bs[br * 8 + 3][bn] = b_reg0.w;
        Bs[br * 8 + 4][bn] = b_reg1.x;
        Bs[br * 8 + 5][bn] = b_reg1.y;
        Bs[br * 8 + 6][bn] = b_reg1.z;
        Bs[br * 8 + 7][bn] = b_reg1.w;
        __syncthreads();

        if (k0 + 16 < II) {
            a_reg  = *(const float4*)(Aptr + k0 + 16);
            b_reg0 = *(const float4*)(Wptr + k0 + 16);
            b_reg1 = *(const float4*)(Wptr + k0 + 20);
        }

#pragma unroll
        for (int k = 0; k < 16; k++) {
            float4 av = *(const float4*)&As[k][tm * 4];
            unsigned long long ap[4];
            ap[0] = pack2(av.x); ap[1] = pack2(av.y);
            ap[2] = pack2(av.z); ap[3] = pack2(av.w);
            ulonglong2 bv0 = *(const ulonglong2*)&Bs[k][tn * 8];
            ulonglong2 bv1 = *(const ulonglong2*)&Bs[k][tn * 8 + 4];
#pragma unroll
            for (int i = 0; i < 4; i++) {
                ffma2(acc[i][0], ap[i], bv0.x);
                ffma2(acc[i][1], ap[i], bv0.y);
                ffma2(acc[i][2], ap[i], bv1.x);
                ffma2(acc[i][3], ap[i], bv1.y);
            }
        }
        __syncthreads();
    }

    // epilogue: m = t*BB + b, t constant per CTA
    const int t = blockIdx.y;
    const int nb = n0 + tn * 8;
    float bia[8];
#pragma unroll
    for (int j = 0; j < 8; j++) bia[j] = bias[nb + j];

#pragma unroll
    for (int i = 0; i < 4; i++) {
        int b = tm * 4 + i;
        float o[8];
        unpack2(acc[i][0], o[0], o[1]);
        unpack2(acc[i][1], o[2], o[3]);
        unpack2(acc[i][2], o[4], o[5]);
        unpack2(acc[i][3], o[6], o[7]);
#pragma unroll
        for (int j = 0; j < 8; j++) o[j] += bia[j];
        float4* dst = (float4*)&out[((size_t)b * TT + t) * DD + nb];
        dst[0] = make_float4(o[0], o[1], o[2], o[3]);
        dst[1] = make_float4(o[4], o[5], o[6], o[7]);
    }
}

// ---------------------------------------------------------------------------
// Stage 2: persistent recurrence. 128 CTAs x 256 threads, d-tile 16.
// h stored transposed [d][b]; W pre-transposed [k][d] with {w,w} duplication
// in smem so the inner loop is: LDS.128(h quad) + LDS.64(w pair) + 2 FFMA2.
// Double-buffered smem -> ONE __syncthreads per 64-k chunk.
// ---------------------------------------------------------------------------
__global__ __launch_bounds__(S2_THREADS) void recur_kernel(float* __restrict__ out)
{
    __shared__ __align__(16) float  Hs[2][S2_KT][BB];          // 32 KB
    __shared__ __align__(16) float2 Ws2[2][S2_KT][S2_DTILE];   // 16 KB

    const int tid = threadIdx.x;
    const int dd  = tid & 15;           // d within tile (also w-loader column)
    const int bq  = tid >> 4;           // batch quad id 0..15
    const int d0  = blockIdx.x * S2_DTILE;
    const int d   = d0 + dd;
    const int b4  = bq * 4;

    // staging coords: f = tid + i*256 -> k = (tid>>4) + i*16, col = tid&15
    const int sk  = tid >> 4;
    const int hc4 = (tid & 15) * 4;

    for (int t = 0; t < TT; t++) {
        const float* hin = g_hT[t & 1];
        float* hout = g_hT[(t + 1) & 1];

        unsigned long long acc0 = 0ull, acc1 = 0ull;   // 4 b-outputs as 2 pairs

        // prefetch chunk 0
        float4 hreg[4]; float wreg[4];
#pragma unroll
        for (int i = 0; i < 4; i++) {
            int k = sk + i * 16;
            hreg[i] = __ldcg((const float4*)&hin[k * BB + hc4]);
            wreg[i] = __ldg(&g_Wt[(size_t)k * DD + d0 + dd]);
        }

        for (int c = 0; c < S2_NCHUNK; c++) {
            const int p = c & 1;
#pragma unroll
            for (int i = 0; i < 4; i++) {
                int k = sk + i * 16;
                *(float4*)&Hs[p][k][hc4] = hreg[i];
                Ws2[p][k][dd] = make_float2(wreg[i], wreg[i]);
            }
            __syncthreads();

            if (c + 1 < S2_NCHUNK) {
                const int kn = (c + 1) * S2_KT;
#pragma unroll
                for (int i = 0; i < 4; i++) {
                    int k = sk + i * 16;
                    hreg[i] = __ldcg((const float4*)&hin[(kn + k) * BB + hc4]);
                    wreg[i] = __ldg(&g_Wt[(size_t)(kn + k) * DD + d0 + dd]);
                }
            }

#pragma unroll
            for (int kk = 0; kk < S2_KT; kk++) {
                unsigned long long w =
                    *(const unsigned long long*)&Ws2[p][kk][dd];
                ulonglong2 hv = *(const ulonglong2*)&Hs[p][kk][b4];
                ffma2(acc0, hv.x, w);
                ffma2(acc1, hv.y, w);
            }
        }

        // epilogue: x = proj + hW ; h_new = 0.5 h + 0.5 tanh(x)
        float hp[4];
        {
            float4 h4 = __ldcg((const float4*)&hin[d * BB + b4]);
            hp[0] = h4.x; hp[1] = h4.y; hp[2] = h4.z; hp[3] = h4.w;
        }
        float av[4];
        unpack2(acc0, av[0], av[1]);
        unpack2(acc1, av[2], av[3]);

        float hn[4];
#pragma unroll
        for (int i = 0; i < 4; i++) {
            size_t oidx = ((size_t)(b4 + i) * TT + t) * DD + d;
            float x = out[oidx] + av[i];
            float v = (1.0f - LEAK) * hp[i] + LEAK * fast_tanh(x);
            hn[i] = v;
            out[oidx] = v;
        }
        *(float4*)&hout[d * BB + b4] = make_float4(hn[0], hn[1], hn[2], hn[3]);

        // grid-wide barrier (skip after the final step)
        if (t < TT - 1) {
            __threadfence();
            __syncthreads();
            if (tid == 0) {
                atomicAdd(&g_bar[t], 1u);
                volatile unsigned int* bp = &g_bar[t];
                while (*bp < (unsigned)S2_NCTA) { __nanosleep(64); }
            }
            __syncthreads();
        }
    }
}

// ---------------------------------------------------------------------------
// Launch
// ---------------------------------------------------------------------------
extern "C" void kernel_launch(void* const* d_in, const int* in_sizes, int n_in,
                              void* d_out, int out_size) {
    (void)in_sizes; (void)n_in; (void)out_size;
    const float* batch   = (const float*)d_in[0];  // [TT, BB, II]
    const float* input_w = (const float*)d_in[1];  // [DD, II]
    const float* res_w   = (const float*)d_in[2];  // [DD, DD]
    const float* bias    = (const float*)d_in[3];  // [DD]
    float* out = (float*)d_out;                    // [BB, TT, DD]

    init_kernel<<<128, 256>>>();

    dim3 gt(DD / 32, DD / 32);          // 64 x 64
    transpose_kernel<<<gt, 256>>>(res_w);

    dim3 g1(DD / 128, TT);              // 16 x 512
    proj_kernel<<<g1, 256>>>(batch, input_w, bias, out);

    recur_kernel<<<S2_NCTA, S2_THREADS>>>(out);
}

// round 10
// speedup vs baseline: 1.9711x; 1.9711x over previous
#include <cuda_runtime.h>

// Problem dims (fixed per reference)
#define TT 512
#define BB 64
#define II 768
#define DD 2048
#define LEAK 0.5f

// Stage-2 persistent config
#define NCTA 128              // 2048/16 d-tiles, 1 CTA/SM (smem-limited)
#define DT 16                 // d-columns per CTA
#define KG 16                 // split-k groups
#define KRANGE 128            // k per group
#define KC 8                  // k per staged chunk (per group)
#define NCHUNK 16             // KRANGE / KC
#define THREADS 256

#define HROW 68                              // padded floats per (j,kg) h-row
#define HS_BUF_FLOATS (KC * KG * HROW)       // 8704
#define HS_BUF_BYTES  (HS_BUF_FLOATS * 4)    // 34816 (x2 buffers = 69632)
#define W_FLOATS (KRANGE * KG * DT)          // 32768
#define W_BYTES  (W_FLOATS * 4)              // 131072
#define RED_STRIDE 9                         // ull per (kg,b) row, padded
#define RED_BYTES (KG * BB * RED_STRIDE * 8) // 73728 (unions the 2 h buffers)
#define SMEM_TOTAL (W_BYTES + RED_BYTES)     // 204800 <= 227 KB

typedef unsigned long long ull;

// Scratch (__device__ globals; no allocations allowed)
__device__ float g_hT[2][DD * BB];      // hidden state transposed [d][b], double-buffered
__device__ unsigned int g_bar[TT];      // per-step grid-barrier counters

// ---------------------------------------------------------------------------
// f32x2 + misc helpers
// ---------------------------------------------------------------------------
__device__ __forceinline__ void ffma2(ull& acc, ull a, ull b) {
    asm("fma.rn.f32x2 %0, %1, %2, %0;" : "+l"(acc) : "l"(a), "l"(b));
}
__device__ __forceinline__ ull addf2(ull a, ull b) {
    ull r; asm("add.rn.f32x2 %0, %1, %2;" : "=l"(r) : "l"(a), "l"(b)); return r;
}
__device__ __forceinline__ ull pack2(float x) {
    ull r; unsigned int u = __float_as_uint(x);
    asm("mov.b64 %0, {%1, %2};" : "=l"(r) : "r"(u), "r"(u));
    return r;
}
__device__ __forceinline__ void unpack2(ull v, float& lo, float& hi) {
    unsigned int a, b;
    asm("mov.b64 {%0, %1}, %2;" : "=r"(a), "=r"(b) : "l"(v));
    lo = __uint_as_float(a); hi = __uint_as_float(b);
}
__device__ __forceinline__ unsigned smem_u32(const void* p) {
    unsigned r;
    asm("{ .reg .u64 t; cvta.to.shared.u64 t, %1; cvt.u32.u64 %0, t; }"
        : "=r"(r) : "l"(p));
    return r;
}
__device__ __forceinline__ void cp16(unsigned dst, const float* src) {
    asm volatile("cp.async.cg.shared.global [%0], [%1], 16;" :: "r"(dst), "l"(src));
}
#define CP_COMMIT() asm volatile("cp.async.commit_group;")
#define CP_WAIT(n)  asm volatile("cp.async.wait_group %0;" :: "n"(n))

__device__ __forceinline__ float fast_tanh(float x) {
    // 1 - 2/(e^{2x}+1): exact +/-1 at saturation
    float e = __expf(2.0f * x);
    return 1.0f - 2.0f / (e + 1.0f);
}

// ---------------------------------------------------------------------------
// Init: zero h0 (both buffers) and barrier counters — every replay
// ---------------------------------------------------------------------------
__global__ void init_kernel() {
    int idx = blockIdx.x * blockDim.x + threadIdx.x;
    int stride = gridDim.x * blockDim.x;
    float* h = (float*)g_hT;
    for (int i = idx; i < 2 * DD * BB; i += stride) h[i] = 0.0f;
    for (int i = idx; i < TT; i += stride) g_bar[i] = 0u;
}

// ---------------------------------------------------------------------------
// Stage 1: proj[t,b,n] = sum_k batch[t,b,k]*W_in[n,k] + bias[n], into out[b,t,n]
// CTA tile 64m x 128n, k-tile 16, 256 threads, microtile 4m x 8n via f32x2.
// ---------------------------------------------------------------------------
__global__ __launch_bounds__(256) void proj_kernel(
    const float* __restrict__ A,      // [TT*BB, II]
    const float* __restrict__ W,      // [DD, II]
    const float* __restrict__ bias,
    float* __restrict__ out)          // [BB, TT, DD]
{
    __shared__ __align__(16) float As[16][68];
    __shared__ __align__(16) float Bs[16][136];

    const int m0 = blockIdx.y * 64;
    const int n0 = blockIdx.x * 128;
    const int tid = threadIdx.x;
    const int tn = tid & 15;
    const int tm = tid >> 4;

    const int am = tid >> 2, aq = tid & 3;
    const int bn = tid >> 1, br = tid & 1;

    ull acc[4][4];
#pragma unroll
    for (int i = 0; i < 4; i++)
#pragma unroll
        for (int j = 0; j < 4; j++) acc[i][j] = 0ull;

    const float* Aptr = A + (size_t)(m0 + am) * II + aq * 4;
    const float* Wptr = W + (size_t)(n0 + bn) * II + br * 8;

    float4 a_reg  = *(const float4*)(Aptr);
    float4 b_reg0 = *(const float4*)(Wptr);
    float4 b_reg1 = *(const float4*)(Wptr + 4);

    for (int k0 = 0; k0 < II; k0 += 16) {
        As[aq * 4 + 0][am] = a_reg.x;
        As[aq * 4 + 1][am] = a_reg.y;
        As[aq * 4 + 2][am] = a_reg.z;
        As[aq * 4 + 3][am] = a_reg.w;
        Bs[br * 8 + 0][bn] = b_reg0.x;
        Bs[br * 8 + 1][bn] = b_reg0.y;
        Bs[br * 8 + 2][bn] = b_reg0.z;
        Bs[br * 8 + 3][bn] = b_reg0.w;
        Bs[br * 8 + 4][bn] = b_reg1.x;
        Bs[br * 8 + 5][bn] = b_reg1.y;
        Bs[br * 8 + 6][bn] = b_reg1.z;
        Bs[br * 8 + 7][bn] = b_reg1.w;
        __syncthreads();

        if (k0 + 16 < II) {
            a_reg  = *(const float4*)(Aptr + k0 + 16);
            b_reg0 = *(const float4*)(Wptr + k0 + 16);
            b_reg1 = *(const float4*)(Wptr + k0 + 20);
        }

#pragma unroll
        for (int k = 0; k < 16; k++) {
            float4 av = *(const float4*)&As[k][tm * 4];
            ull ap[4];
            ap[0] = pack2(av.x); ap[1] = pack2(av.y);
            ap[2] = pack2(av.z); ap[3] = pack2(av.w);
            ulonglong2 bv0 = *(const ulonglong2*)&Bs[k][tn * 8];
            ulonglong2 bv1 = *(const ulonglong2*)&Bs[k][tn * 8 + 4];
#pragma unroll
            for (int i = 0; i < 4; i++) {
                ffma2(acc[i][0], ap[i], bv0.x);
                ffma2(acc[i][1], ap[i], bv0.y);
                ffma2(acc[i][2], ap[i], bv1.x);
                ffma2(acc[i][3], ap[i], bv1.y);
            }
        }
        __syncthreads();
    }

    const int t = blockIdx.y;
    const int nb = n0 + tn * 8;
    float bia[8];
#pragma unroll
    for (int j = 0; j < 8; j++) bia[j] = bias[nb + j];

#pragma unroll
    for (int i = 0; i < 4; i++) {
        int b = tm * 4 + i;
        float o[8];
        unpack2(acc[i][0], o[0], o[1]);
        unpack2(acc[i][1], o[2], o[3]);
        unpack2(acc[i][2], o[4], o[5]);
        unpack2(acc[i][3], o[6], o[7]);
#pragma unroll
        for (int j = 0; j < 8; j++) o[j] += bia[j];
        float4* dst = (float4*)&out[((size_t)b * TT + t) * DD + nb];
        dst[0] = make_float4(o[0], o[1], o[2], o[3]);
        dst[1] = make_float4(o[4], o[5], o[6], o[7]);
    }
}

// ---------------------------------------------------------------------------
// Stage 2: persistent recurrence, register-blocked 8b x 8d, split-k x16.
//   - W_res CTA slice resident in smem for all 512 steps (interleaved layout).
//   - h streamed via cp.async.cg, double-buffered.
//   - split-k partials reduced through smem (unions the h buffers).
// Thread map: tid = kg*16 + sub; sub = bg*2 + dg.
//   kg: k-group (128 k each); bg: 8 batch rows; dg: 8 d columns.
// ---------------------------------------------------------------------------
__global__ __launch_bounds__(THREADS, 1) void recur_kernel(
    const float* __restrict__ resw,   // [DD, DD] row-major
    float* __restrict__ out)          // [BB, TT, DD]: proj in, h out
{
    extern __shared__ __align__(16) char smem[];
    float* Ws = (float*)smem;                        // [kk 0..127][kg][16 d]
    float* Hs = (float*)(smem + W_BYTES);            // [2][KC][KG][HROW]
    ull*  red = (ull*)(smem + W_BYTES);              // union: [KG*BB][RED_STRIDE]
    const unsigned Hs_base = smem_u32(Hs);

    const int tid = threadIdx.x;
    const int d0  = blockIdx.x * DT;
    const int kg  = tid >> 4;
    const int sub = tid & 15;
    const int bg  = sub >> 1;
    const int dg  = sub & 1;

    // One-time W_res slice load, interleaved: Ws[(kk*KG + kg)*DT + d] = resw[d0+d][kg*128+kk]
    for (int e = tid; e < DT * DD; e += THREADS) {
        int d = e >> 11;              // 0..15
        int k = e & 2047;             // coalesced along k
        int kgx = k >> 7, kkx = k & 127;
        Ws[(kkx * KG + kgx) * DT + d] = resw[(size_t)(d0 + d) * DD + k];
    }
    __syncthreads();

    // Staging descriptors: 8 x 16B per thread per 32KB chunk
    unsigned sm_off[8]; int gl_off[8];
#pragma unroll
    for (int j = 0; j < 8; j++) {
        int s = tid + j * 256;
        int b4  = (s & 15) << 2;
        int kgx = (s >> 4) & 15;
        int jx  = s >> 8;             // 0..7
        sm_off[j] = (unsigned)(((jx * KG + kgx) * HROW + b4) * 4);
        gl_off[j] = kgx * (KRANGE * BB) + jx * BB + b4;
    }

    // epilogue coords: thread owns b = tid>>2, d = d0 + (tid&3)*4 .. +3
    const int eb = tid >> 2;
    const int ed = (tid & 3) * 4;
    const int edp = (tid & 3) * 2;    // ull-pair index

    for (int t = 0; t < TT; t++) {
        const float* hin = g_hT[t & 1];
        float* hout = g_hT[(t + 1) & 1];

        ull acc[8][4];
#pragma unroll
        for (int i = 0; i < 8; i++)
#pragma unroll
            for (int j = 0; j < 4; j++) acc[i][j] = 0ull;

        // stage chunk 0 -> buffer 0
#pragma unroll
        for (int j = 0; j < 8; j++)
            cp16(Hs_base + sm_off[j], hin + gl_off[j]);
        CP_COMMIT();

        for (int c = 0; c < NCHUNK; c++) {
            const int p = c & 1;
            if (c + 1 < NCHUNK) {
                const unsigned soff = (unsigned)((c + 1) & 1) * HS_BUF_BYTES;
                const int goff = (c + 1) * (KC * BB);
#pragma unroll
                for (int j = 0; j < 8; j++)
                    cp16(Hs_base + soff + sm_off[j], hin + goff + gl_off[j]);
                CP_COMMIT();
                CP_WAIT(1);
            } else {
                CP_WAIT(0);
            }
            __syncthreads();

            const float* hbuf = Hs + p * HS_BUF_FLOATS;
#pragma unroll
            for (int j = 0; j < KC; j++) {
                const float* hrow = hbuf + (j * KG + kg) * HROW + bg * 8;
                float4 h0 = *(const float4*)hrow;
                float4 h1 = *(const float4*)(hrow + 4);
                const float* wrow = Ws + ((c * KC + j) * KG + kg) * DT + dg * 8;
                ulonglong2 w0 = *(const ulonglong2*)wrow;        // {d0,d1},{d2,d3}
                ulonglong2 w1 = *(const ulonglong2*)(wrow + 4);  // {d4,d5},{d6,d7}
                float hv[8] = {h0.x, h0.y, h0.z, h0.w, h1.x, h1.y, h1.z, h1.w};
#pragma unroll
                for (int i = 0; i < 8; i++) {
                    ull hp = pack2(hv[i]);
                    ffma2(acc[i][0], hp, w0.x);
                    ffma2(acc[i][1], hp, w0.y);
                    ffma2(acc[i][2], hp, w1.x);
                    ffma2(acc[i][3], hp, w1.y);
                }
            }
            __syncthreads();
        }

        // split-k reduction through smem (red unions Hs; safe after sync)
#pragma unroll
        for (int i = 0; i < 8; i++) {
            ull* rrow = red + (unsigned)(kg * BB + bg * 8 + i) * RED_STRIDE + dg * 4;
            rrow[0] = acc[i][0]; rrow[1] = acc[i][1];
            rrow[2] = acc[i][2]; rrow[3] = acc[i][3];
        }
        __syncthreads();

        ull s0 = 0ull, s1 = 0ull;
#pragma unroll
        for (int g = 0; g < KG; g++) {
            const ull* rr = red + (unsigned)(g * BB + eb) * RED_STRIDE + edp;
            s0 = addf2(s0, rr[0]);
            s1 = addf2(s1, rr[1]);
        }

        // epilogue: x = proj + hW ; h_new = 0.5 h + 0.5 tanh(x)
        float a0, a1, a2, a3;
        unpack2(s0, a0, a1);
        unpack2(s1, a2, a3);
        const int dglob = d0 + ed;

        float4 p4 = *(const float4*)&out[((size_t)eb * TT + t) * DD + dglob];
        float hp0 = __ldcg(&hin[(size_t)(dglob + 0) * BB + eb]);
        float hp1 = __ldcg(&hin[(size_t)(dglob + 1) * BB + eb]);
        float hp2 = __ldcg(&hin[(size_t)(dglob + 2) * BB + eb]);
        float hp3 = __ldcg(&hin[(size_t)(dglob + 3) * BB + eb]);

        float hn0 = (1.0f - LEAK) * hp0 + LEAK * fast_tanh(p4.x + a0);
        float hn1 = (1.0f - LEAK) * hp1 + LEAK * fast_tanh(p4.y + a1);
        float hn2 = (1.0f - LEAK) * hp2 + LEAK * fast_tanh(p4.z + a2);
        float hn3 = (1.0f - LEAK) * hp3 + LEAK * fast_tanh(p4.w + a3);

        hout[(size_t)(dglob + 0) * BB + eb] = hn0;
        hout[(size_t)(dglob + 1) * BB + eb] = hn1;
        hout[(size_t)(dglob + 2) * BB + eb] = hn2;
        hout[(size_t)(dglob + 3) * BB + eb] = hn3;
        *(float4*)&out[((size_t)eb * TT + t) * DD + dglob] =
            make_float4(hn0, hn1, hn2, hn3);

        // grid-wide barrier (skip after the final step)
        if (t < TT - 1) {
            __threadfence();
            __syncthreads();
            if (tid == 0) {
                atomicAdd(&g_bar[t], 1u);
                volatile unsigned int* bp = &g_bar[t];
                while (*bp < (unsigned)NCTA) { __nanosleep(32); }
            }
            __syncthreads();
        }
    }
}

// ---------------------------------------------------------------------------
// Launch
// ---------------------------------------------------------------------------
extern "C" void kernel_launch(void* const* d_in, const int* in_sizes, int n_in,
                              void* d_out, int out_size) {
    (void)in_sizes; (void)n_in; (void)out_size;
    const float* batch   = (const float*)d_in[0];  // [TT, BB, II]
    const float* input_w = (const float*)d_in[1];  // [DD, II]
    const float* res_w   = (const float*)d_in[2];  // [DD, DD]
    const float* bias    = (const float*)d_in[3];  // [DD]
    float* out = (float*)d_out;                    // [BB, TT, DD]

    cudaFuncSetAttribute(recur_kernel,
                         cudaFuncAttributeMaxDynamicSharedMemorySize, SMEM_TOTAL);

    init_kernel<<<128, 256>>>();

    dim3 g1(DD / 128, TT);              // 16 x 512
    proj_kernel<<<g1, 256>>>(batch, input_w, bias, out);

    recur_kernel<<<NCTA, THREADS, SMEM_TOTAL>>>(res_w, out);
}